// round 17
// baseline (speedup 1.0000x reference)
#include <cuda_runtime.h>

// Haar-DWT L1 loss, B=32,C=1,H=512,W=512 fp32 x2 inputs.
// DWT is linear -> butterfly the per-pixel diff.
//
// FINAL (converged, 16 rounds): 512 CTAs x 128 threads x 8 octs with
// chip-interleaved stride addressing, evict_last v8.b32 loads, PDL-overlapped
// zero node, scaled atomicAdd epilogue. 6.26TB/s achieved on the mandatory
// 67.1MB read — ~92-96% of the B300 practical streaming ceiling.
// Band across 6 confirmation runs: 10.72-10.98us.
//
// Falsified alternatives: occupancy 19-79% (equal), grid 512/608/1024/2048
// (equal), TMA bulk staging (-50%), bulk L2 prefetch + contiguous per-CTA
// regions (-16%; interleaved striding is load-bearing for LTS-slice
// parallelism), __ldcs/default cache policy (neutral), v4 vs v8 loads
// (neutral), fused single-kernel epilogues (worse), red.v2 (neutral).
//
// One "oct" = 8 consecutive floats of row 2r + the 8 floats below in row 2r+1
// (from both tensors) = 4 Haar blocks. N_OCTS = 32*256*64 = 524,288.
#define N_BLOCKS_TOTAL 2097152.0f

#define CTAS    512
#define THREADS 128
#define OCTS    8
#define STRIDE  (CTAS * THREADS)   // 65536; CTAS*THREADS*OCTS == 524288 exactly

__global__ void zero_out_kernel(float* out) {
    if (threadIdx.x < 2) out[threadIdx.x] = 0.0f;
    cudaTriggerProgrammaticLaunchCompletion();
}

// 32-byte load with L2 evict_last residency hint (v8 required for the hint).
__device__ __forceinline__ void ldg_keep8(const float* p, float4& a, float4& b) {
    asm("ld.global.L2::evict_last.v8.b32 {%0,%1,%2,%3,%4,%5,%6,%7}, [%8];"
        : "=f"(a.x), "=f"(a.y), "=f"(a.z), "=f"(a.w),
          "=f"(b.x), "=f"(b.y), "=f"(b.z), "=f"(b.w)
        : "l"(p));
}

// Butterfly 2 Haar blocks from one float4-pair of diffs (row0 quad, row1 quad).
__device__ __forceinline__ void haar_quad(
    const float4& r0, const float4& r1, float& lo, float& hi)
{
    // r0 = (a0,b0,a1,b1), r1 = (c0,d0,c1,d1); 0.5 folded into final scale.
    {
        const float p = r0.x + r0.y, qq = r1.x + r1.y;
        const float u = r0.x - r0.y, v  = r1.x - r1.y;
        lo += fabsf(p + qq);
        hi += fabsf(qq - p) + fabsf(u + v) + fabsf(u - v);
    }
    {
        const float p = r0.z + r0.w, qq = r1.z + r1.w;
        const float u = r0.z - r0.w, v  = r1.z - r1.w;
        lo += fabsf(p + qq);
        hi += fabsf(qq - p) + fabsf(u + v) + fabsf(u - v);
    }
}

__device__ __forceinline__ float4 f4sub(const float4& x, const float4& y) {
    return make_float4(x.x - y.x, x.y - y.y, x.z - y.z, x.w - y.w);
}

__global__ __launch_bounds__(THREADS) void haar_loss_kernel(
    const float* __restrict__ in,
    const float* __restrict__ tgt,
    float* __restrict__ out)
{
    const int q0 = blockIdx.x * THREADS + threadIdx.x;

    float lo = 0.0f, hi = 0.0f;

    #pragma unroll
    for (int j = 0; j < OCTS; j++) {
        const int q     = q0 + j * STRIDE;
        const int c8    = q & 63;              // oct column within row-pair
        const int base0 = 8 * (2 * q - c8);    // float offset of row 2r
        const int base1 = base0 + 512;         // row 2r+1

        float4 i0a, i0b, i1a, i1b, t0a, t0b, t1a, t1b;
        ldg_keep8(in  + base0, i0a, i0b);
        ldg_keep8(in  + base1, i1a, i1b);
        ldg_keep8(tgt + base0, t0a, t0b);
        ldg_keep8(tgt + base1, t1a, t1b);

        haar_quad(f4sub(i0a, t0a), f4sub(i1a, t1a), lo, hi);
        haar_quad(f4sub(i0b, t0b), f4sub(i1b, t1b), lo, hi);
    }

    // warp reduction
    #pragma unroll
    for (int o = 16; o > 0; o >>= 1) {
        lo += __shfl_xor_sync(0xffffffffu, lo, o);
        hi += __shfl_xor_sync(0xffffffffu, hi, o);
    }

    __shared__ float slo[THREADS / 32], shi[THREADS / 32];
    const int warp = threadIdx.x >> 5;
    const int lane = threadIdx.x & 31;
    if (lane == 0) { slo[warp] = lo; shi[warp] = hi; }
    __syncthreads();

    if (threadIdx.x < 32) {
        lo = (lane < THREADS / 32) ? slo[lane] : 0.0f;
        hi = (lane < THREADS / 32) ? shi[lane] : 0.0f;
        #pragma unroll
        for (int o = 2; o > 0; o >>= 1) {
            lo += __shfl_xor_sync(0xffffffffu, lo, o);
            hi += __shfl_xor_sync(0xffffffffu, hi, o);
        }
        if (lane == 0) {
            // Wait for zero_out to have committed before touching out.
            cudaGridDependencySynchronize();
            const float sL = 0.5f / N_BLOCKS_TOTAL;
            const float sH = 0.5f / (3.0f * N_BLOCKS_TOTAL);
            atomicAdd(&out[0], lo * sL);
            atomicAdd(&out[1], hi * sH);
        }
    }
}

extern "C" void kernel_launch(void* const* d_in, const int* in_sizes, int n_in,
                              void* d_out, int out_size) {
    const float* in  = (const float*)d_in[0];
    const float* tgt = (const float*)d_in[1];
    float* out = (float*)d_out;

    zero_out_kernel<<<1, 32>>>(out);

    // PDL: main kernel may start while zero_out is resident; in-kernel
    // cudaGridDependencySynchronize() orders the output atomics.
    cudaLaunchConfig_t cfg = {};
    cfg.gridDim  = dim3(CTAS);
    cfg.blockDim = dim3(THREADS);
    cfg.stream   = 0;
    cudaLaunchAttribute attr[1];
    attr[0].id = cudaLaunchAttributeProgrammaticStreamSerialization;
    attr[0].val.programmaticStreamSerializationAllowed = 1;
    cfg.attrs    = attr;
    cfg.numAttrs = 1;
    cudaLaunchKernelEx(&cfg, haar_loss_kernel, in, tgt, out);
}